// round 1
// baseline (speedup 1.0000x reference)
#include <cuda_runtime.h>

// Problem constants
#define B_  2
#define N_  4096
#define E_  256
#define H_  8
#define TAU_ 32
#define HD_ 32
#define M_TOT (B_ * N_)          // 8192 rows
#define SCALE_ 0.17677669529663687f  // 1/sqrt(32)

// Scratch for projected Q', K', V'  (each 8 MB fp32)
__device__ float g_q[M_TOT * E_];
__device__ float g_k[M_TOT * E_];
__device__ float g_v[M_TOT * E_];

// ---------------------------------------------------------------------------
// Projection GEMM:  O[r][e] = bias[e] + sum_k X[r][k] * W[e][k]
// X: (8192 x 256) row-major, W: (256 x 256) row-major (out = X @ W^T + b)
// Tile: BM=128, BN=64, BK=16, 256 threads, each thread 8x4 outputs.
// grid = (E_/64, M_TOT/128, 3)  — z selects q/k/v input.
// ---------------------------------------------------------------------------
__global__ __launch_bounds__(256, 2)
void proj_kernel(const float* __restrict__ Xq, const float* __restrict__ Xk,
                 const float* __restrict__ Xv, const float* __restrict__ W,
                 const float* __restrict__ bias)
{
    constexpr int BM = 128, BN = 64, BK = 16, TM = 8, TN = 4;

    const float* X;
    float* O;
    if (blockIdx.z == 0)      { X = Xq; O = g_q; }
    else if (blockIdx.z == 1) { X = Xk; O = g_k; }
    else                      { X = Xv; O = g_v; }

    __shared__ float sA[BK][BM];   // transposed A tile
    __shared__ float sB[BK][BN];   // transposed B(=W) tile

    const int tid = threadIdx.x;
    const int tx = tid & 15;       // 0..15 -> cols tx*4..+3
    const int ty = tid >> 4;       // 0..15 -> rows ty*8..+7
    const int rowBase = blockIdx.y * BM;
    const int colBase = blockIdx.x * BN;

    float acc[TM][TN];
    #pragma unroll
    for (int i = 0; i < TM; i++)
        #pragma unroll
        for (int j = 0; j < TN; j++) acc[i][j] = 0.f;

    for (int k0 = 0; k0 < E_; k0 += BK) {
        // Load A tile: 128 rows x 16 k = 512 float4 -> 2 per thread
        #pragma unroll
        for (int i = 0; i < 2; i++) {
            int idx = tid + i * 256;          // 0..511
            int r   = idx >> 2;               // 0..127
            int c4  = (idx & 3) << 2;         // 0,4,8,12
            float4 a = *(const float4*)&X[(rowBase + r) * E_ + k0 + c4];
            sA[c4 + 0][r] = a.x; sA[c4 + 1][r] = a.y;
            sA[c4 + 2][r] = a.z; sA[c4 + 3][r] = a.w;
        }
        // Load B tile: 64 e-rows x 16 k = 256 float4 -> 1 per thread
        {
            int idx = tid;                    // 0..255
            int r   = idx >> 2;               // 0..63
            int c4  = (idx & 3) << 2;
            float4 w = *(const float4*)&W[(colBase + r) * E_ + k0 + c4];
            sB[c4 + 0][r] = w.x; sB[c4 + 1][r] = w.y;
            sB[c4 + 2][r] = w.z; sB[c4 + 3][r] = w.w;
        }
        __syncthreads();

        #pragma unroll
        for (int kk = 0; kk < BK; kk++) {
            float aF[TM], bF[TN];
            #pragma unroll
            for (int i = 0; i < TM; i++) aF[i] = sA[kk][ty * TM + i];
            #pragma unroll
            for (int j = 0; j < TN; j++) bF[j] = sB[kk][tx * TN + j];
            #pragma unroll
            for (int i = 0; i < TM; i++)
                #pragma unroll
                for (int j = 0; j < TN; j++)
                    acc[i][j] += aF[i] * bF[j];
        }
        __syncthreads();
    }

    // Epilogue: add bias, float4 stores
    float bj[TN];
    #pragma unroll
    for (int j = 0; j < TN; j++) bj[j] = bias[colBase + tx * TN + j];

    #pragma unroll
    for (int i = 0; i < TM; i++) {
        int r = rowBase + ty * TM + i;
        float4 o;
        o.x = acc[i][0] + bj[0];
        o.y = acc[i][1] + bj[1];
        o.z = acc[i][2] + bj[2];
        o.w = acc[i][3] + bj[3];
        *(float4*)&O[r * E_ + colBase + tx * TN] = o;
    }
}

// ---------------------------------------------------------------------------
// Sliding-window attention.
// Window for query n covers key positions n-31 .. n; positions < 0 use the
// projected pad row, which equals the bias vector (proj(0) = b).
// grid = (N_/64, H_, B_), 256 threads (8 warps).
// Warp w handles queries qi = w, w+8, ... within the 64-query chunk.
// Lane t computes score for window slot t; softmax via warp shuffles;
// output dim d handled by lane d in the V pass.
// ---------------------------------------------------------------------------
__global__ __launch_bounds__(256)
void attn_kernel(const float* __restrict__ bias, float* __restrict__ out)
{
    __shared__ float sQ[64][32];
    __shared__ float sK[95][33];   // stride 33 -> conflict-free diagonal access
    __shared__ float sV[95][33];

    const int n0 = blockIdx.x * 64;
    const int h  = blockIdx.y;
    const int b  = blockIdx.z;
    const int tid = threadIdx.x;
    const int base = (b * N_) * E_ + h * HD_;   // offset of (b, n=0, h, d=0)

    // Load Q chunk: 64 rows x 32 d
    for (int idx = tid; idx < 64 * 32; idx += 256) {
        int r = idx >> 5, d = idx & 31;
        sQ[r][d] = g_q[base + (n0 + r) * E_ + d];
    }
    // Load K,V rows n0-31 .. n0+63  (95 rows)
    for (int idx = tid; idx < 95 * 32; idx += 256) {
        int r = idx >> 5, d = idx & 31;
        int n = n0 - 31 + r;
        float kk, vv;
        if (n < 0) {
            kk = bias[h * HD_ + d];   // projected pad row == bias
            vv = kk;
        } else {
            kk = g_k[base + n * E_ + d];
            vv = g_v[base + n * E_ + d];
        }
        sK[r][d] = kk;
        sV[r][d] = vv;
    }
    __syncthreads();

    const int w    = tid >> 5;
    const int lane = tid & 31;

    for (int qi = w; qi < 64; qi += 8) {
        // lane = window slot t : score = q . k_{n-31+t}
        float s = 0.f;
        #pragma unroll
        for (int d = 0; d < 32; d++) s += sQ[qi][d] * sK[qi + lane][d];
        s *= SCALE_;

        // warp softmax over 32 slots
        float m = s;
        #pragma unroll
        for (int off = 16; off; off >>= 1)
            m = fmaxf(m, __shfl_xor_sync(0xffffffffu, m, off));
        float e = __expf(s - m);
        float sum = e;
        #pragma unroll
        for (int off = 16; off; off >>= 1)
            sum += __shfl_xor_sync(0xffffffffu, sum, off);
        float p = e / sum;           // lane t holds prob of slot t

        // lane = output dim d : o_d = sum_t p_t * V[t][d]
        float o = 0.f;
        #pragma unroll
        for (int t = 0; t < 32; t++)
            o += __shfl_sync(0xffffffffu, p, t) * sV[qi + t][lane];

        out[base + (n0 + qi) * E_ + lane] = o;
    }
}

// ---------------------------------------------------------------------------
extern "C" void kernel_launch(void* const* d_in, const int* in_sizes, int n_in,
                              void* d_out, int out_size)
{
    const float* q = (const float*)d_in[0];
    const float* k = (const float*)d_in[1];
    const float* v = (const float*)d_in[2];
    const float* W = (const float*)d_in[3];
    const float* b = (const float*)d_in[4];
    float* out = (float*)d_out;

    dim3 gProj(E_ / 64, M_TOT / 128, 3);
    proj_kernel<<<gProj, 256>>>(q, k, v, W, b);

    dim3 gAttn(N_ / 64, H_, B_);
    attn_kernel<<<gAttn, 256>>>(b, out);
}

// round 3
// speedup vs baseline: 1.9841x; 1.9841x over previous
#include <cuda_runtime.h>
#include <cuda_bf16.h>
#include <cstdint>

// Problem constants
#define B_  2
#define N_  4096
#define E_  256
#define H_  8
#define TAU_ 32
#define HD_ 32
#define M_TOT (B_ * N_)              // 8192
#define SCALE_ 0.17677669529663687f  // 1/sqrt(32)

// Scratch for projected Q', K', V'
__device__ float g_q[M_TOT * E_];
__device__ float g_k[M_TOT * E_];
__device__ float g_v[M_TOT * E_];

// ===========================================================================
// Portable tensor-core path: ldmatrix + mma.sync (compute_80-era PTX, maps to
// LDSM/HMMA on sm_103a — tcgen05 PTX is rejected by this toolchain's ptxas).
// ===========================================================================
__device__ __forceinline__ uint32_t smem_u32(const void* p) {
    uint32_t a;
    asm("{ .reg .u64 t; cvta.to.shared.u64 t, %1; cvt.u32.u64 %0, t; }"
        : "=r"(a) : "l"(p));
    return a;
}

#define LDSM_X4(r0, r1, r2, r3, addr) \
    asm volatile("ldmatrix.sync.aligned.m8n8.x4.shared.b16 {%0,%1,%2,%3}, [%4];" \
                 : "=r"(r0), "=r"(r1), "=r"(r2), "=r"(r3) : "r"(addr))

#define MMA_BF16(c, a, b) \
    asm volatile("mma.sync.aligned.m16n8k16.row.col.f32.bf16.bf16.f32 " \
                 "{%0,%1,%2,%3}, {%4,%5,%6,%7}, {%8,%9}, {%0,%1,%2,%3};" \
                 : "+f"((c)[0]), "+f"((c)[1]), "+f"((c)[2]), "+f"((c)[3]) \
                 : "r"((a)[0]), "r"((a)[1]), "r"((a)[2]), "r"((a)[3]), \
                   "r"((b)[0]), "r"((b)[1]))

// SMEM bf16 tile: 128 rows x 64 k, 128B rows, XOR swizzle on 16B granules.
__device__ __forceinline__ uint32_t swz(int row, int kbyte) {
    return (uint32_t)(row * 128 + ((((kbyte >> 4)) ^ (row & 7)) << 4) + (kbyte & 15));
}

__device__ __forceinline__ uint32_t pack_bf2(__nv_bfloat16 a, __nv_bfloat16 b) {
    __nv_bfloat162 t = __halves2bfloat162(a, b);
    return *reinterpret_cast<uint32_t*>(&t);
}

// Split a float4 into bf16 hi / lo (residual) pairs and store 8B to each region
__device__ __forceinline__ void split_sts(float4 v, uint32_t ahi, uint32_t alo) {
    __nv_bfloat16 hx = __float2bfloat16_rn(v.x);
    __nv_bfloat16 hy = __float2bfloat16_rn(v.y);
    __nv_bfloat16 hz = __float2bfloat16_rn(v.z);
    __nv_bfloat16 hw = __float2bfloat16_rn(v.w);
    __nv_bfloat16 lx = __float2bfloat16_rn(v.x - __bfloat162float(hx));
    __nv_bfloat16 ly = __float2bfloat16_rn(v.y - __bfloat162float(hy));
    __nv_bfloat16 lz = __float2bfloat16_rn(v.z - __bfloat162float(hz));
    __nv_bfloat16 lw = __float2bfloat16_rn(v.w - __bfloat162float(hw));
    uint32_t h0 = pack_bf2(hx, hy), h1 = pack_bf2(hz, hw);
    uint32_t l0 = pack_bf2(lx, ly), l1 = pack_bf2(lz, lw);
    asm volatile("st.shared.v2.b32 [%0], {%1,%2};" :: "r"(ahi), "r"(h0), "r"(h1));
    asm volatile("st.shared.v2.b32 [%0], {%1,%2};" :: "r"(alo), "r"(l0), "r"(l1));
}

// SMEM offsets (dynamic, 64 KB total)
#define SM_A_HI 0
#define SM_A_LO 16384
#define SM_B_HI 32768
#define SM_B_LO 49152
#define SMEM_TOTAL 65536

// ===========================================================================
// Projection GEMM: O[128,128] tile = X[128,256] @ W[128,256]^T + bias
// grid = (2 n-halves, 64 m-tiles, 3 matrices), 256 threads (8 warps 4x2).
// Warp tile 32x64; bf16-split: acc += Ahi*Bhi + Ahi*Blo + Alo*Bhi.
// ===========================================================================
__global__ __launch_bounds__(256, 1)
void proj_mma_kernel(const float* __restrict__ Xq, const float* __restrict__ Xk,
                     const float* __restrict__ Xv, const float* __restrict__ W,
                     const float* __restrict__ bias)
{
    extern __shared__ char smem[];
    const uint32_t sb = smem_u32(smem);
    const int tid = threadIdx.x;
    const int wid = tid >> 5, lane = tid & 31;
    const int wm = wid & 3;          // 0..3 (M direction, 32 rows each)
    const int wn = wid >> 2;         // 0..1 (N direction, 64 cols each)

    const float* X;
    float* O;
    if (blockIdx.z == 0)      { X = Xq; O = g_q; }
    else if (blockIdx.z == 1) { X = Xk; O = g_k; }
    else                      { X = Xv; O = g_v; }

    const int rowA0 = blockIdx.y * 128;
    const int rowB0 = blockIdx.x * 128;

    float acc[2][8][4];
    #pragma unroll
    for (int i = 0; i < 2; i++)
        #pragma unroll
        for (int j = 0; j < 8; j++)
            #pragma unroll
            for (int q = 0; q < 4; q++) acc[i][j][q] = 0.f;

    // Per-thread LDG coords: 2048 float4 per operand per chunk, 8 per thread
    float4 ra[8], rb[8];

    // ldmatrix base addresses (per-lane, row/kb parts added per use)
    const int sub = lane >> 3, r8 = lane & 7;

    // ---- prefetch chunk 0 ----
    #pragma unroll
    for (int i = 0; i < 8; i++) {
        int idx = tid + i * 256;
        int row = idx >> 4;
        int k4  = (idx & 15) << 2;
        ra[i] = *(const float4*)&X[(rowA0 + row) * E_ + k4];
        rb[i] = *(const float4*)&W[(rowB0 + row) * E_ + k4];
    }

    for (int c = 0; c < 4; c++) {
        __syncthreads();   // previous chunk's MMAs done before overwriting smem
        #pragma unroll
        for (int i = 0; i < 8; i++) {
            int idx = tid + i * 256;
            int row = idx >> 4;
            int k4  = (idx & 15) << 2;
            uint32_t sw = swz(row, k4 * 2);
            split_sts(ra[i], sb + SM_A_HI + sw, sb + SM_A_LO + sw);
            split_sts(rb[i], sb + SM_B_HI + sw, sb + SM_B_LO + sw);
        }
        __syncthreads();

        if (c < 3) {
            const int k0 = (c + 1) * 64;
            #pragma unroll
            for (int i = 0; i < 8; i++) {
                int idx = tid + i * 256;
                int row = idx >> 4;
                int k4  = (idx & 15) << 2;
                ra[i] = *(const float4*)&X[(rowA0 + row) * E_ + k0 + k4];
                rb[i] = *(const float4*)&W[(rowB0 + row) * E_ + k0 + k4];
            }
        }

        // ---- MMA over 4 k-steps of 16 ----
        #pragma unroll
        for (int ks = 0; ks < 4; ks++) {
            uint32_t ahi[2][4], alo[2][4];
            #pragma unroll
            for (int mt = 0; mt < 2; mt++) {
                int arow = wm * 32 + mt * 16 + (sub & 1) * 8 + r8;
                int akb  = ks * 32 + (sub >> 1) * 16;
                uint32_t sw = swz(arow, akb);
                LDSM_X4(ahi[mt][0], ahi[mt][1], ahi[mt][2], ahi[mt][3],
                        sb + SM_A_HI + sw);
                LDSM_X4(alo[mt][0], alo[mt][1], alo[mt][2], alo[mt][3],
                        sb + SM_A_LO + sw);
            }
            uint32_t bhi[4][4], blo[4][4];
            #pragma unroll
            for (int np = 0; np < 4; np++) {
                int nrow = wn * 64 + np * 16 + (sub >> 1) * 8 + r8;
                int bkb  = ks * 32 + (sub & 1) * 16;
                uint32_t sw = swz(nrow, bkb);
                LDSM_X4(bhi[np][0], bhi[np][1], bhi[np][2], bhi[np][3],
                        sb + SM_B_HI + sw);
                LDSM_X4(blo[np][0], blo[np][1], blo[np][2], blo[np][3],
                        sb + SM_B_LO + sw);
            }
            #pragma unroll
            for (int mt = 0; mt < 2; mt++) {
                #pragma unroll
                for (int np = 0; np < 4; np++) {
                    MMA_BF16(acc[mt][np * 2 + 0], ahi[mt], &bhi[np][0]);
                    MMA_BF16(acc[mt][np * 2 + 1], ahi[mt], &bhi[np][2]);
                    MMA_BF16(acc[mt][np * 2 + 0], ahi[mt], &blo[np][0]);
                    MMA_BF16(acc[mt][np * 2 + 1], ahi[mt], &blo[np][2]);
                    MMA_BF16(acc[mt][np * 2 + 0], alo[mt], &bhi[np][0]);
                    MMA_BF16(acc[mt][np * 2 + 1], alo[mt], &bhi[np][2]);
                }
            }
        }
    }

    // ---- epilogue: add bias, store fp32 ----
    const int qrow = lane >> 2;          // 0..7
    const int qcol = (lane & 3) * 2;     // 0,2,4,6
    #pragma unroll
    for (int mt = 0; mt < 2; mt++) {
        int r = rowA0 + wm * 32 + mt * 16 + qrow;
        #pragma unroll
        for (int nt = 0; nt < 8; nt++) {
            int cb = rowB0 + wn * 64 + nt * 8 + qcol;
            float b0 = bias[cb], b1 = bias[cb + 1];
            float2 o0 = { acc[mt][nt][0] + b0, acc[mt][nt][1] + b1 };
            float2 o1 = { acc[mt][nt][2] + b0, acc[mt][nt][3] + b1 };
            *(float2*)&O[(size_t)r * E_ + cb]       = o0;
            *(float2*)&O[(size_t)(r + 8) * E_ + cb] = o1;
        }
    }
}

// ===========================================================================
// Sliding-window attention, MIO-optimized (LDS.128 + XOR swizzle).
// grid = (N/64, H, B), 256 threads (8 warps). Warp w owns queries w+8j.
// ===========================================================================
__global__ __launch_bounds__(256)
void attn_kernel(const float* __restrict__ bias, float* __restrict__ out)
{
    __shared__ float4 sQ4[64 * 8];
    __shared__ float4 sK4[95 * 8];
    __shared__ float4 sV4[95 * 8];
    __shared__ float  sP[64][33];

    const int n0 = blockIdx.x * 64;
    const int h  = blockIdx.y;
    const int b  = blockIdx.z;
    const int tid = threadIdx.x;
    const int base = (b * N_) * E_ + h * HD_;

    for (int idx = tid; idx < 64 * 8; idx += 256) {
        int r = idx >> 3, c = idx & 7;
        sQ4[idx] = *(const float4*)&g_q[base + (n0 + r) * E_ + c * 4];
    }
    for (int idx = tid; idx < 95 * 8; idx += 256) {
        int r = idx >> 3, c = idx & 7;
        int n = n0 - 31 + r;
        float4 kf, vf;
        if (n < 0) {
            kf = *(const float4*)&bias[h * HD_ + c * 4];  // proj(0) == bias
            vf = kf;
        } else {
            kf = *(const float4*)&g_k[base + n * E_ + c * 4];
            vf = *(const float4*)&g_v[base + n * E_ + c * 4];
        }
        int cc = c ^ (r & 7);
        sK4[r * 8 + cc] = kf;
        sV4[r * 8 + cc] = vf;
    }
    __syncthreads();

    const int w    = tid >> 5;
    const int lane = tid & 31;

    // Phase 1: scores + warp softmax; prob of slot t lands in sP[qi][t]
    #pragma unroll
    for (int j = 0; j < 8; j++) {
        int qi  = w + 8 * j;
        int row = qi + lane;
        int rx  = row & 7;
        const float4* kr = &sK4[row * 8];
        const float4* qr = &sQ4[qi * 8];
        float s = 0.f;
        #pragma unroll
        for (int c = 0; c < 8; c++) {
            float4 kf = kr[c ^ rx];
            float4 qf = qr[c];
            s += qf.x * kf.x + qf.y * kf.y + qf.z * kf.z + qf.w * kf.w;
        }
        s *= SCALE_;
        float m = s;
        #pragma unroll
        for (int off = 16; off; off >>= 1)
            m = fmaxf(m, __shfl_xor_sync(0xffffffffu, m, off));
        float e = __expf(s - m);
        float sum = e;
        #pragma unroll
        for (int off = 16; off; off >>= 1)
            sum += __shfl_xor_sync(0xffffffffu, sum, off);
        sP[qi][lane] = e / sum;
    }
    __syncwarp();

    // Phase 2: lane = (qsub = lane>>3, d4 = lane&7); 4 queries x 8 dims
    const int qsub = lane >> 3;
    const int d4   = lane & 7;
    #pragma unroll
    for (int g = 0; g < 2; g++) {
        int qi = w + 8 * (g * 4 + qsub);
        float4 acc = {0.f, 0.f, 0.f, 0.f};
        #pragma unroll
        for (int t = 0; t < 32; t++) {
            float p  = sP[qi][t];
            int row  = qi + t;
            float4 vf = sV4[row * 8 + (d4 ^ (row & 7))];
            acc.x += p * vf.x;
            acc.y += p * vf.y;
            acc.z += p * vf.z;
            acc.w += p * vf.w;
        }
        *(float4*)&out[base + (n0 + qi) * E_ + d4 * 4] = acc;
    }
}

// ===========================================================================
extern "C" void kernel_launch(void* const* d_in, const int* in_sizes, int n_in,
                              void* d_out, int out_size)
{
    const float* q = (const float*)d_in[0];
    const float* k = (const float*)d_in[1];
    const float* v = (const float*)d_in[2];
    const float* W = (const float*)d_in[3];
    const float* b = (const float*)d_in[4];
    float* out = (float*)d_out;

    cudaFuncSetAttribute(proj_mma_kernel,
                         cudaFuncAttributeMaxDynamicSharedMemorySize, SMEM_TOTAL);

    dim3 gProj(2, 64, 3);
    proj_mma_kernel<<<gProj, 256, SMEM_TOTAL>>>(q, k, v, W, b);

    dim3 gAttn(N_ / 64, H_, B_);
    attn_kernel<<<gAttn, 256>>>(b, out);
}

// round 4
// speedup vs baseline: 2.1221x; 1.0696x over previous
#include <cuda_runtime.h>
#include <cuda_bf16.h>
#include <cstdint>

// Problem constants
#define B_  2
#define N_  4096
#define E_  256
#define H_  8
#define TAU_ 32
#define HD_ 32
#define M_TOT (B_ * N_)              // 8192
#define SCALE_ 0.17677669529663687f  // 1/sqrt(32)

// Scratch for projected Q', K', V'
__device__ float g_q[M_TOT * E_];
__device__ float g_k[M_TOT * E_];
__device__ float g_v[M_TOT * E_];

// ===========================================================================
// Portable tensor-core path: ldmatrix + mma.sync (fallback LDSM/HMMA on
// sm_103a — tcgen05 PTX is rejected by this toolchain's ptxas).
// ===========================================================================
__device__ __forceinline__ uint32_t smem_u32(const void* p) {
    uint32_t a;
    asm("{ .reg .u64 t; cvta.to.shared.u64 t, %1; cvt.u32.u64 %0, t; }"
        : "=r"(a) : "l"(p));
    return a;
}

#define LDSM_X4(r0, r1, r2, r3, addr) \
    asm volatile("ldmatrix.sync.aligned.m8n8.x4.shared.b16 {%0,%1,%2,%3}, [%4];" \
                 : "=r"(r0), "=r"(r1), "=r"(r2), "=r"(r3) : "r"(addr))

#define MMA_BF16(c, a, b) \
    asm volatile("mma.sync.aligned.m16n8k16.row.col.f32.bf16.bf16.f32 " \
                 "{%0,%1,%2,%3}, {%4,%5,%6,%7}, {%8,%9}, {%0,%1,%2,%3};" \
                 : "+f"((c)[0]), "+f"((c)[1]), "+f"((c)[2]), "+f"((c)[3]) \
                 : "r"((a)[0]), "r"((a)[1]), "r"((a)[2]), "r"((a)[3]), \
                   "r"((b)[0]), "r"((b)[1]))

#define STS_B16(addr, v) \
    asm volatile("st.shared.b16 [%0], %1;" :: "r"(addr), "h"(v))

__device__ __forceinline__ uint32_t pack_bf2(__nv_bfloat16 a, __nv_bfloat16 b) {
    __nv_bfloat162 t = __halves2bfloat162(a, b);
    return *reinterpret_cast<uint32_t*>(&t);
}
__device__ __forceinline__ unsigned short bf_bits(__nv_bfloat16 h) {
    return *reinterpret_cast<unsigned short*>(&h);
}

// Split a float4 into bf16 hi / lo (residual) and store 8B to each region
__device__ __forceinline__ void split_sts(float4 v, uint32_t ahi, uint32_t alo) {
    __nv_bfloat16 hx = __float2bfloat16_rn(v.x);
    __nv_bfloat16 hy = __float2bfloat16_rn(v.y);
    __nv_bfloat16 hz = __float2bfloat16_rn(v.z);
    __nv_bfloat16 hw = __float2bfloat16_rn(v.w);
    __nv_bfloat16 lx = __float2bfloat16_rn(v.x - __bfloat162float(hx));
    __nv_bfloat16 ly = __float2bfloat16_rn(v.y - __bfloat162float(hy));
    __nv_bfloat16 lz = __float2bfloat16_rn(v.z - __bfloat162float(hz));
    __nv_bfloat16 lw = __float2bfloat16_rn(v.w - __bfloat162float(hw));
    uint32_t h0 = pack_bf2(hx, hy), h1 = pack_bf2(hz, hw);
    uint32_t l0 = pack_bf2(lx, ly), l1 = pack_bf2(lz, lw);
    asm volatile("st.shared.v2.b32 [%0], {%1,%2};" :: "r"(ahi), "r"(h0), "r"(h1));
    asm volatile("st.shared.v2.b32 [%0], {%1,%2};" :: "r"(alo), "r"(l0), "r"(l1));
}

// ===========================================================================
// Projection GEMM (unchanged from R3): O[128,128] = X[128,256] @ W[.,256]^T + b
// ===========================================================================
__device__ __forceinline__ uint32_t swz(int row, int kbyte) {
    return (uint32_t)(row * 128 + ((((kbyte >> 4)) ^ (row & 7)) << 4) + (kbyte & 15));
}

#define SM_A_HI 0
#define SM_A_LO 16384
#define SM_B_HI 32768
#define SM_B_LO 49152
#define PROJ_SMEM 65536

__global__ __launch_bounds__(256, 1)
void proj_mma_kernel(const float* __restrict__ Xq, const float* __restrict__ Xk,
                     const float* __restrict__ Xv, const float* __restrict__ W,
                     const float* __restrict__ bias)
{
    extern __shared__ char smem[];
    const uint32_t sb = smem_u32(smem);
    const int tid = threadIdx.x;
    const int wid = tid >> 5, lane = tid & 31;
    const int wm = wid & 3;
    const int wn = wid >> 2;

    const float* X;
    float* O;
    if (blockIdx.z == 0)      { X = Xq; O = g_q; }
    else if (blockIdx.z == 1) { X = Xk; O = g_k; }
    else                      { X = Xv; O = g_v; }

    const int rowA0 = blockIdx.y * 128;
    const int rowB0 = blockIdx.x * 128;

    float acc[2][8][4];
    #pragma unroll
    for (int i = 0; i < 2; i++)
        #pragma unroll
        for (int j = 0; j < 8; j++)
            #pragma unroll
            for (int q = 0; q < 4; q++) acc[i][j][q] = 0.f;

    float4 ra[8], rb[8];
    const int sub = lane >> 3, r8 = lane & 7;

    #pragma unroll
    for (int i = 0; i < 8; i++) {
        int idx = tid + i * 256;
        int row = idx >> 4;
        int k4  = (idx & 15) << 2;
        ra[i] = *(const float4*)&X[(rowA0 + row) * E_ + k4];
        rb[i] = *(const float4*)&W[(rowB0 + row) * E_ + k4];
    }

    for (int c = 0; c < 4; c++) {
        __syncthreads();
        #pragma unroll
        for (int i = 0; i < 8; i++) {
            int idx = tid + i * 256;
            int row = idx >> 4;
            int k4  = (idx & 15) << 2;
            uint32_t sw = swz(row, k4 * 2);
            split_sts(ra[i], sb + SM_A_HI + sw, sb + SM_A_LO + sw);
            split_sts(rb[i], sb + SM_B_HI + sw, sb + SM_B_LO + sw);
        }
        __syncthreads();

        if (c < 3) {
            const int k0 = (c + 1) * 64;
            #pragma unroll
            for (int i = 0; i < 8; i++) {
                int idx = tid + i * 256;
                int row = idx >> 4;
                int k4  = (idx & 15) << 2;
                ra[i] = *(const float4*)&X[(rowA0 + row) * E_ + k0 + k4];
                rb[i] = *(const float4*)&W[(rowB0 + row) * E_ + k0 + k4];
            }
        }

        #pragma unroll
        for (int ks = 0; ks < 4; ks++) {
            uint32_t ahi[2][4], alo[2][4];
            #pragma unroll
            for (int mt = 0; mt < 2; mt++) {
                int arow = wm * 32 + mt * 16 + (sub & 1) * 8 + r8;
                int akb  = ks * 32 + (sub >> 1) * 16;
                uint32_t sw = swz(arow, akb);
                LDSM_X4(ahi[mt][0], ahi[mt][1], ahi[mt][2], ahi[mt][3],
                        sb + SM_A_HI + sw);
                LDSM_X4(alo[mt][0], alo[mt][1], alo[mt][2], alo[mt][3],
                        sb + SM_A_LO + sw);
            }
            uint32_t bhi[4][4], blo[4][4];
            #pragma unroll
            for (int np = 0; np < 4; np++) {
                int nrow = wn * 64 + np * 16 + (sub >> 1) * 8 + r8;
                int bkb  = ks * 32 + (sub & 1) * 16;
                uint32_t sw = swz(nrow, bkb);
                LDSM_X4(bhi[np][0], bhi[np][1], bhi[np][2], bhi[np][3],
                        sb + SM_B_HI + sw);
                LDSM_X4(blo[np][0], blo[np][1], blo[np][2], blo[np][3],
                        sb + SM_B_LO + sw);
            }
            #pragma unroll
            for (int mt = 0; mt < 2; mt++) {
                #pragma unroll
                for (int np = 0; np < 4; np++) {
                    MMA_BF16(acc[mt][np * 2 + 0], ahi[mt], &bhi[np][0]);
                    MMA_BF16(acc[mt][np * 2 + 1], ahi[mt], &bhi[np][2]);
                    MMA_BF16(acc[mt][np * 2 + 0], ahi[mt], &blo[np][0]);
                    MMA_BF16(acc[mt][np * 2 + 1], ahi[mt], &blo[np][2]);
                    MMA_BF16(acc[mt][np * 2 + 0], alo[mt], &bhi[np][0]);
                    MMA_BF16(acc[mt][np * 2 + 1], alo[mt], &bhi[np][2]);
                }
            }
        }
    }

    const int qrow = lane >> 2;
    const int qcol = (lane & 3) * 2;
    #pragma unroll
    for (int mt = 0; mt < 2; mt++) {
        int r = rowA0 + wm * 32 + mt * 16 + qrow;
        #pragma unroll
        for (int nt = 0; nt < 8; nt++) {
            int cb = rowB0 + wn * 64 + nt * 8 + qcol;
            float b0 = bias[cb], b1 = bias[cb + 1];
            float2 o0 = { acc[mt][nt][0] + b0, acc[mt][nt][1] + b1 };
            float2 o1 = { acc[mt][nt][2] + b0, acc[mt][nt][3] + b1 };
            *(float2*)&O[(size_t)r * E_ + cb]       = o0;
            *(float2*)&O[(size_t)(r + 8) * E_ + cb] = o1;
        }
    }
}

// ===========================================================================
// MMA-based sliding-window attention.
// Band split: queries [0,32) use K/V rows [0,64); queries [32,64) rows [32,96).
// S_mh[32x64] = Q_mh . K_mh^T ; softmax on band ; O_mh = P_mh[32x64] . V_mh.
// All matmuls: bf16-split 3-pass (hi*hi + hi*lo + lo*hi), fp32 accum.
// SMEM layouts (padded strides -> conflict-free LDSM):
//   Q:  64 rows x 32k bf16, stride 80B      (hi/lo)
//   K:  96 rows x 32k bf16, stride 80B      (hi/lo)  row r = key n0-31+r
//   VT: 32 rows(d) x 96k(r) bf16, stride 208B (hi/lo)
//   P:  2 blocks x 32 rows x 64k bf16, stride 144B (hi/lo), zero-filled
//   S:  2 blocks x 32 rows x 66 f32 (264B stride)
// ===========================================================================
#define AT_QHI  0
#define AT_QLO  5120
#define AT_KHI  10240
#define AT_KLO  17920
#define AT_VTHI 25600
#define AT_VTLO 32256
#define AT_PHI  38912
#define AT_PLO  48128
#define AT_S    57344
#define ATTN_SMEM 74240

__global__ __launch_bounds__(256, 1)
void attn_kernel(const float* __restrict__ bias, float* __restrict__ out)
{
    extern __shared__ char smem[];
    const uint32_t sb = smem_u32(smem);

    const int n0 = blockIdx.x * 64;
    const int h  = blockIdx.y;
    const int b  = blockIdx.z;
    const int tid = threadIdx.x;
    const int base = (b * N_) * E_ + h * HD_;

    // ---- zero-fill P (hi+lo contiguous: 18432 B) ----
    for (int i = tid; i < 18432 / 16; i += 256) {
        uint4 z = {0, 0, 0, 0};
        *(uint4*)(smem + AT_PHI + i * 16) = z;
    }

    // ---- fill Q (64 x 32) ----
    for (int idx = tid; idx < 64 * 8; idx += 256) {
        int r = idx >> 3, d4 = idx & 7;
        float4 qv = *(const float4*)&g_q[base + (n0 + r) * E_ + d4 * 4];
        uint32_t off = r * 80 + d4 * 8;
        split_sts(qv, sb + AT_QHI + off, sb + AT_QLO + off);
    }

    // ---- fill K (96 rows, row 95 = zero pad) and V^T ----
    for (int idx = tid; idx < 96 * 8; idx += 256) {
        int r = idx >> 3, d4 = idx & 7;
        int n = n0 - 31 + r;
        float4 kf, vf;
        if (r == 95) {
            kf = make_float4(0.f, 0.f, 0.f, 0.f);
            vf = kf;
        } else if (n < 0) {
            kf = *(const float4*)&bias[h * HD_ + d4 * 4];  // proj(0) == bias
            vf = kf;
        } else {
            kf = *(const float4*)&g_k[base + n * E_ + d4 * 4];
            vf = *(const float4*)&g_v[base + n * E_ + d4 * 4];
        }
        uint32_t koff = r * 80 + d4 * 8;
        split_sts(kf, sb + AT_KHI + koff, sb + AT_KLO + koff);

        // V^T: element (r, d) -> VT[d][r]
        const float ve[4] = {vf.x, vf.y, vf.z, vf.w};
        #pragma unroll
        for (int e = 0; e < 4; e++) {
            int d = d4 * 4 + e;
            __nv_bfloat16 hi = __float2bfloat16_rn(ve[e]);
            __nv_bfloat16 lo = __float2bfloat16_rn(ve[e] - __bfloat162float(hi));
            uint32_t voff = d * 208 + r * 2;
            STS_B16(sb + AT_VTHI + voff, bf_bits(hi));
            STS_B16(sb + AT_VTLO + voff, bf_bits(lo));
        }
    }
    __syncthreads();

    const int wid  = tid >> 5;
    const int lane = tid & 31;
    const int sub = lane >> 3, r8 = lane & 7;
    const int qrow = lane >> 2, qcol = (lane & 3) * 2;

    // ================= Score MMA =================
    // warp: mh = wid>>2; ww = wid&3: wm = ww&1 (16 m-rows), wn = ww>>1 (32 n)
    {
        const int mh = wid >> 2;
        const int ww = wid & 3;
        const int wm = ww & 1;
        const int wn = ww >> 1;

        float acc_s[2][2][4];
        #pragma unroll
        for (int i = 0; i < 2; i++)
            #pragma unroll
            for (int j = 0; j < 2; j++)
                #pragma unroll
                for (int q = 0; q < 4; q++) acc_s[i][j][q] = 0.f;

        #pragma unroll
        for (int ks = 0; ks < 2; ks++) {
            int arow = mh * 32 + wm * 16 + (sub & 1) * 8 + r8;
            int akb  = ks * 32 + (sub >> 1) * 16;
            uint32_t aoff = arow * 80 + akb;
            uint32_t ahi[4], alo[4];
            LDSM_X4(ahi[0], ahi[1], ahi[2], ahi[3], sb + AT_QHI + aoff);
            LDSM_X4(alo[0], alo[1], alo[2], alo[3], sb + AT_QLO + aoff);

            #pragma unroll
            for (int np = 0; np < 2; np++) {
                int nr = mh * 32 + wn * 32 + np * 16 + (sub >> 1) * 8 + r8;
                int kb = ks * 32 + (sub & 1) * 16;
                uint32_t boff = nr * 80 + kb;
                uint32_t bhi[4], blo[4];
                LDSM_X4(bhi[0], bhi[1], bhi[2], bhi[3], sb + AT_KHI + boff);
                LDSM_X4(blo[0], blo[1], blo[2], blo[3], sb + AT_KLO + boff);

                MMA_BF16(acc_s[np][0], ahi, &bhi[0]);
                MMA_BF16(acc_s[np][1], ahi, &bhi[2]);
                MMA_BF16(acc_s[np][0], ahi, &blo[0]);
                MMA_BF16(acc_s[np][1], ahi, &blo[2]);
                MMA_BF16(acc_s[np][0], alo, &bhi[0]);
                MMA_BF16(acc_s[np][1], alo, &bhi[2]);
            }
        }

        // epilogue -> S block
        float* Sblk = (float*)(smem + AT_S + mh * 8448);
        #pragma unroll
        for (int np = 0; np < 2; np++)
            #pragma unroll
            for (int hf = 0; hf < 2; hf++) {
                int lr  = wm * 16 + qrow;
                int col = wn * 32 + np * 16 + hf * 8 + qcol;
                float2 s0 = { acc_s[np][hf][0], acc_s[np][hf][1] };
                float2 s1 = { acc_s[np][hf][2], acc_s[np][hf][3] };
                *(float2*)&Sblk[lr * 66 + col]       = s0;
                *(float2*)&Sblk[(lr + 8) * 66 + col] = s1;
            }
    }
    __syncthreads();

    // ================= Softmax on the band =================
    // warp wid handles queries wid*8 .. wid*8+7; lane = window slot t.
    #pragma unroll
    for (int j = 0; j < 8; j++) {
        int qi = wid * 8 + j;
        int mh = qi >> 5;
        int lr = qi & 31;
        float s = *(const float*)(smem + AT_S + mh * 8448 + lr * 264
                                  + (lr + lane) * 4);
        s *= SCALE_;
        float m = s;
        #pragma unroll
        for (int off = 16; off; off >>= 1)
            m = fmaxf(m, __shfl_xor_sync(0xffffffffu, m, off));
        float e = __expf(s - m);
        float sum = e;
        #pragma unroll
        for (int off = 16; off; off >>= 1)
            sum += __shfl_xor_sync(0xffffffffu, sum, off);
        float p = e / sum;

        __nv_bfloat16 ph = __float2bfloat16_rn(p);
        __nv_bfloat16 pl = __float2bfloat16_rn(p - __bfloat162float(ph));
        uint32_t poff = mh * 4608 + lr * 144 + (lr + lane) * 2;
        STS_B16(sb + AT_PHI + poff, bf_bits(ph));
        STS_B16(sb + AT_PLO + poff, bf_bits(pl));
    }
    __syncthreads();

    // ================= P . V MMA =================
    // warp: mh = wid>>2; ww = wid&3: wm = ww&1 (16 m), wn = ww>>1 (16 n)
    {
        const int mh = wid >> 2;
        const int ww = wid & 3;
        const int wm = ww & 1;
        const int wn = ww >> 1;

        float acc_o[2][4];
        #pragma unroll
        for (int j = 0; j < 2; j++)
            #pragma unroll
            for (int q = 0; q < 4; q++) acc_o[j][q] = 0.f;

        #pragma unroll
        for (int ks = 0; ks < 4; ks++) {
            uint32_t aoff = mh * 4608
                          + (wm * 16 + (sub & 1) * 8 + r8) * 144
                          + ks * 32 + (sub >> 1) * 16;
            uint32_t phi[4], plo[4];
            LDSM_X4(phi[0], phi[1], phi[2], phi[3], sb + AT_PHI + aoff);
            LDSM_X4(plo[0], plo[1], plo[2], plo[3], sb + AT_PLO + aoff);

            uint32_t boff = (wn * 16 + (sub >> 1) * 8 + r8) * 208
                          + mh * 64 + ks * 32 + (sub & 1) * 16;
            uint32_t vhi[4], vlo[4];
            LDSM_X4(vhi[0], vhi[1], vhi[2], vhi[3], sb + AT_VTHI + boff);
            LDSM_X4(vlo[0], vlo[1], vlo[2], vlo[3], sb + AT_VTLO + boff);

            MMA_BF16(acc_o[0], phi, &vhi[0]);
            MMA_BF16(acc_o[1], phi, &vhi[2]);
            MMA_BF16(acc_o[0], phi, &vlo[0]);
            MMA_BF16(acc_o[1], phi, &vlo[2]);
            MMA_BF16(acc_o[0], plo, &vhi[0]);
            MMA_BF16(acc_o[1], plo, &vhi[2]);
        }

        // epilogue -> gmem
        #pragma unroll
        for (int nf = 0; nf < 2; nf++) {
            int n = n0 + mh * 32 + wm * 16 + qrow;
            int d = wn * 16 + nf * 8 + qcol;
            float2 o0 = { acc_o[nf][0], acc_o[nf][1] };
            float2 o1 = { acc_o[nf][2], acc_o[nf][3] };
            *(float2*)&out[base + (size_t)n * E_ + d]       = o0;
            *(float2*)&out[base + (size_t)(n + 8) * E_ + d] = o1;
        }
    }
}

// ===========================================================================
extern "C" void kernel_launch(void* const* d_in, const int* in_sizes, int n_in,
                              void* d_out, int out_size)
{
    const float* q = (const float*)d_in[0];
    const float* k = (const float*)d_in[1];
    const float* v = (const float*)d_in[2];
    const float* W = (const float*)d_in[3];
    const float* b = (const float*)d_in[4];
    float* out = (float*)d_out;

    cudaFuncSetAttribute(proj_mma_kernel,
                         cudaFuncAttributeMaxDynamicSharedMemorySize, PROJ_SMEM);
    cudaFuncSetAttribute(attn_kernel,
                         cudaFuncAttributeMaxDynamicSharedMemorySize, ATTN_SMEM);

    dim3 gProj(2, 64, 3);
    proj_mma_kernel<<<gProj, 256, PROJ_SMEM>>>(q, k, v, W, b);

    dim3 gAttn(N_ / 64, H_, B_);
    attn_kernel<<<gAttn, 256, ATTN_SMEM>>>(b, out);
}

// round 8
// speedup vs baseline: 2.2662x; 1.0679x over previous
#include <cuda_runtime.h>
#include <cuda_bf16.h>
#include <cstdint>

// Problem constants
#define B_  2
#define N_  4096
#define E_  256
#define H_  8
#define TAU_ 32
#define HD_ 32
#define M_TOT (B_ * N_)              // 8192
#define SCALE_ 0.17677669529663687f  // 1/sqrt(32)

// bf16-split inputs (filled by convert_kernel)
#define XT (3 * M_TOT * E_)
#define WT (E_ * E_)
__device__ __nv_bfloat16 g_xhi[XT], g_xlo[XT];
__device__ __nv_bfloat16 g_whi[WT], g_wlo[WT];

// bf16-split projected Q', K', V' (filled by proj_mma_kernel)
__device__ __nv_bfloat16 g_qh[M_TOT * E_], g_ql[M_TOT * E_];
__device__ __nv_bfloat16 g_kh[M_TOT * E_], g_kl[M_TOT * E_];
__device__ __nv_bfloat16 g_vh[M_TOT * E_], g_vl[M_TOT * E_];

// ===========================================================================
// Helpers (LDSM/HMMA fallback path; tcgen05 PTX rejected by this toolchain)
// ===========================================================================
__device__ __forceinline__ uint32_t smem_u32(const void* p) {
    uint32_t a;
    asm("{ .reg .u64 t; cvta.to.shared.u64 t, %1; cvt.u32.u64 %0, t; }"
        : "=r"(a) : "l"(p));
    return a;
}

#define LDSM_X4(r0, r1, r2, r3, addr) \
    asm volatile("ldmatrix.sync.aligned.m8n8.x4.shared.b16 {%0,%1,%2,%3}, [%4];" \
                 : "=r"(r0), "=r"(r1), "=r"(r2), "=r"(r3) : "r"(addr))

#define LDSM_X4_T(r0, r1, r2, r3, addr) \
    asm volatile("ldmatrix.sync.aligned.m8n8.x4.trans.shared.b16 {%0,%1,%2,%3}, [%4];" \
                 : "=r"(r0), "=r"(r1), "=r"(r2), "=r"(r3) : "r"(addr))

#define MMA_BF16(c, a, b) \
    asm volatile("mma.sync.aligned.m16n8k16.row.col.f32.bf16.bf16.f32 " \
                 "{%0,%1,%2,%3}, {%4,%5,%6,%7}, {%8,%9}, {%0,%1,%2,%3};" \
                 : "+f"((c)[0]), "+f"((c)[1]), "+f"((c)[2]), "+f"((c)[3]) \
                 : "r"((a)[0]), "r"((a)[1]), "r"((a)[2]), "r"((a)[3]), \
                   "r"((b)[0]), "r"((b)[1]))

__device__ __forceinline__ uint32_t pack_bf2(__nv_bfloat16 a, __nv_bfloat16 b) {
    __nv_bfloat162 t = __halves2bfloat162(a, b);
    return *reinterpret_cast<uint32_t*>(&t);
}

// Split two floats into packed bf16 (hi) and packed residual (lo)
__device__ __forceinline__ void split2(float x, float y, uint32_t& hi, uint32_t& lo) {
    __nv_bfloat16 hx = __float2bfloat16_rn(x);
    __nv_bfloat16 hy = __float2bfloat16_rn(y);
    __nv_bfloat16 lx = __float2bfloat16_rn(x - __bfloat162float(hx));
    __nv_bfloat16 ly = __float2bfloat16_rn(y - __bfloat162float(hy));
    hi = pack_bf2(hx, hy);
    lo = pack_bf2(lx, ly);
}

// ===========================================================================
// Kernel 0: fp32 -> bf16 hi/lo split of X (q,k,v) and W
// ===========================================================================
__global__ void convert_kernel(const float* __restrict__ q, const float* __restrict__ k,
                               const float* __restrict__ v, const float* __restrict__ w)
{
    const int i4 = blockIdx.x * blockDim.x + threadIdx.x;
    const int R4 = M_TOT * E_ / 4;  // float4s per matrix
    const int X4 = 3 * R4;
    const int W4 = WT / 4;

    float4 val;
    __nv_bfloat16 *dh, *dl;
    int gi;
    if (i4 < X4) {
        int reg = i4 / R4;
        int l   = i4 - reg * R4;
        const float* s = (reg == 0) ? q : (reg == 1) ? k : v;
        val = ((const float4*)s)[l];
        dh = g_xhi; dl = g_xlo; gi = i4 * 4;
    } else if (i4 < X4 + W4) {
        int l = i4 - X4;
        val = ((const float4*)w)[l];
        dh = g_whi; dl = g_wlo; gi = l * 4;
    } else {
        return;
    }
    uint32_t h0, l0, h1, l1;
    split2(val.x, val.y, h0, l0);
    split2(val.z, val.w, h1, l1);
    uint2 H = {h0, h1}, L = {l0, l1};
    *(uint2*)&dh[gi] = H;
    *(uint2*)&dl[gi] = L;
}

// ===========================================================================
// Kernel 1: projection GEMM (pure LDSM/HMMA hot loop, pre-split inputs).
// O[128,128] tile = X[128,256] @ W[.,256]^T + bias, written as bf16 hi/lo.
// grid = (2 n-halves, 64 m-tiles, 3 matrices), 256 threads (8 warps 4x2).
// Each K-chunk per array: 128 rows x 64 k bf16 = 128 B/row = 1024 uint4.
// ===========================================================================
__device__ __forceinline__ uint32_t swz(int row, int kbyte) {
    return (uint32_t)(row * 128 + ((((kbyte >> 4)) ^ (row & 7)) << 4) + (kbyte & 15));
}

#define SM_A_HI 0
#define SM_A_LO 16384
#define SM_B_HI 32768
#define SM_B_LO 49152
#define PROJ_SMEM 65536

__global__ __launch_bounds__(256, 1)
void proj_mma_kernel(const float* __restrict__ bias)
{
    extern __shared__ char smem[];
    const uint32_t sb = smem_u32(smem);
    const int tid = threadIdx.x;
    const int wid = tid >> 5, lane = tid & 31;
    const int wm = wid & 3;
    const int wn = wid >> 2;
    const int z = blockIdx.z;

    const __nv_bfloat16* Ah = g_xhi + (size_t)z * M_TOT * E_;
    const __nv_bfloat16* Al = g_xlo + (size_t)z * M_TOT * E_;
    __nv_bfloat16 *Oh, *Ol;
    if (z == 0)      { Oh = g_qh; Ol = g_ql; }
    else if (z == 1) { Oh = g_kh; Ol = g_kl; }
    else             { Oh = g_vh; Ol = g_vl; }

    const int rowA0 = blockIdx.y * 128;
    const int rowB0 = blockIdx.x * 128;

    float acc[2][8][4];
    #pragma unroll
    for (int i = 0; i < 2; i++)
        #pragma unroll
        for (int j = 0; j < 8; j++)
            #pragma unroll
            for (int q = 0; q < 4; q++) acc[i][j][q] = 0.f;

    const int sub = lane >> 3, r8 = lane & 7;

    // 1024 uint4 per array per chunk -> 4 per thread
    uint4 pah[4], pal[4], pbh[4], pbl[4];
    #pragma unroll
    for (int i = 0; i < 4; i++) {
        int idx = tid + i * 256;           // 0..1023
        int row = idx >> 3;                // 0..127
        int gc  = idx & 7;                 // 0..7 (k elements gc*8..+7)
        int ea  = (rowA0 + row) * E_ + gc * 8;
        int eb  = (rowB0 + row) * E_ + gc * 8;
        pah[i] = *(const uint4*)&Ah[ea];
        pal[i] = *(const uint4*)&Al[ea];
        pbh[i] = *(const uint4*)&g_whi[eb];
        pbl[i] = *(const uint4*)&g_wlo[eb];
    }

    for (int c = 0; c < 4; c++) {
        __syncthreads();
        #pragma unroll
        for (int i = 0; i < 4; i++) {
            int idx = tid + i * 256;
            int row = idx >> 3;
            int gc  = idx & 7;
            uint32_t sw = swz(row, gc * 16);
            *(uint4*)(smem + SM_A_HI + sw) = pah[i];
            *(uint4*)(smem + SM_A_LO + sw) = pal[i];
            *(uint4*)(smem + SM_B_HI + sw) = pbh[i];
            *(uint4*)(smem + SM_B_LO + sw) = pbl[i];
        }
        __syncthreads();

        if (c < 3) {
            const int k0 = (c + 1) * 64;
            #pragma unroll
            for (int i = 0; i < 4; i++) {
                int idx = tid + i * 256;
                int row = idx >> 3;
                int gc  = idx & 7;
                int ea  = (rowA0 + row) * E_ + k0 + gc * 8;
                int eb  = (rowB0 + row) * E_ + k0 + gc * 8;
                pah[i] = *(const uint4*)&Ah[ea];
                pal[i] = *(const uint4*)&Al[ea];
                pbh[i] = *(const uint4*)&g_whi[eb];
                pbl[i] = *(const uint4*)&g_wlo[eb];
            }
        }

        #pragma unroll
        for (int ks = 0; ks < 4; ks++) {
            uint32_t ahi[2][4], alo[2][4];
            #pragma unroll
            for (int mt = 0; mt < 2; mt++) {
                int arow = wm * 32 + mt * 16 + (sub & 1) * 8 + r8;
                int akb  = ks * 32 + (sub >> 1) * 16;
                uint32_t sw = swz(arow, akb);
                LDSM_X4(ahi[mt][0], ahi[mt][1], ahi[mt][2], ahi[mt][3],
                        sb + SM_A_HI + sw);
                LDSM_X4(alo[mt][0], alo[mt][1], alo[mt][2], alo[mt][3],
                        sb + SM_A_LO + sw);
            }
            uint32_t bhi[4][4], blo[4][4];
            #pragma unroll
            for (int np = 0; np < 4; np++) {
                int nrow = wn * 64 + np * 16 + (sub >> 1) * 8 + r8;
                int bkb  = ks * 32 + (sub & 1) * 16;
                uint32_t sw = swz(nrow, bkb);
                LDSM_X4(bhi[np][0], bhi[np][1], bhi[np][2], bhi[np][3],
                        sb + SM_B_HI + sw);
                LDSM_X4(blo[np][0], blo[np][1], blo[np][2], blo[np][3],
                        sb + SM_B_LO + sw);
            }
            #pragma unroll
            for (int mt = 0; mt < 2; mt++) {
                #pragma unroll
                for (int np = 0; np < 4; np++) {
                    MMA_BF16(acc[mt][np * 2 + 0], ahi[mt], &bhi[np][0]);
                    MMA_BF16(acc[mt][np * 2 + 1], ahi[mt], &bhi[np][2]);
                    MMA_BF16(acc[mt][np * 2 + 0], ahi[mt], &blo[np][0]);
                    MMA_BF16(acc[mt][np * 2 + 1], ahi[mt], &blo[np][2]);
                    MMA_BF16(acc[mt][np * 2 + 0], alo[mt], &bhi[np][0]);
                    MMA_BF16(acc[mt][np * 2 + 1], alo[mt], &bhi[np][2]);
                }
            }
        }
    }

    // Epilogue: add bias, split to bf16 hi/lo, store
    const int qrow = lane >> 2;
    const int qcol = (lane & 3) * 2;
    #pragma unroll
    for (int mt = 0; mt < 2; mt++) {
        int r = rowA0 + wm * 32 + mt * 16 + qrow;
        #pragma unroll
        for (int nt = 0; nt < 8; nt++) {
            int cb = rowB0 + wn * 64 + nt * 8 + qcol;
            float b0 = bias[cb], b1 = bias[cb + 1];
            uint32_t h, l;
            split2(acc[mt][nt][0] + b0, acc[mt][nt][1] + b1, h, l);
            *(uint32_t*)&Oh[(size_t)r * E_ + cb] = h;
            *(uint32_t*)&Ol[(size_t)r * E_ + cb] = l;
            split2(acc[mt][nt][2] + b0, acc[mt][nt][3] + b1, h, l);
            *(uint32_t*)&Oh[(size_t)(r + 8) * E_ + cb] = h;
            *(uint32_t*)&Ol[(size_t)(r + 8) * E_ + cb] = l;
        }
    }
}

// ===========================================================================
// Kernel 2: per-warp register flash attention.
// CTA = 128 queries x (b,h); warp g owns queries [g*16, g*16+16).
// S = Q16x32 . K48x32^T (banded window), in-register mask+softmax,
// S-frags repacked to A-frags, O = P16x48 . V48x32 (V via ldmatrix.trans).
// Smem rows stride 80B -> conflict-free LDSM (both trans and non-trans).
// ===========================================================================
#define AQ_HI 0
#define AQ_LO 10240
#define AK_HI 20480
#define AK_LO 33280
#define AV_HI 46080
#define AV_LO 58880
#define ATTN_SMEM 71680

__global__ __launch_bounds__(256)
void attn_kernel(const float* __restrict__ bias, float* __restrict__ out)
{
    extern __shared__ char smem[];
    const uint32_t sb = smem_u32(smem);

    const int n0 = blockIdx.x * 128;
    const int h  = blockIdx.y;
    const int b  = blockIdx.z;
    const int tid = threadIdx.x;
    const size_t basee = (size_t)(b * N_) * E_ + h * HD_;

    // ---- fill Q (128 rows x 32 d = 64 B/row), row stride 80B ----
    for (int idx = tid; idx < 512; idx += 256) {
        int r = idx >> 2, gc = idx & 3;
        size_t e = basee + (size_t)(n0 + r) * E_ + gc * 8;
        *(uint4*)(smem + AQ_HI + r * 80 + gc * 16) = *(const uint4*)&g_qh[e];
        *(uint4*)(smem + AQ_LO + r * 80 + gc * 16) = *(const uint4*)&g_ql[e];
    }
    // ---- fill K,V (160 rows; row r = key n0-31+r; pad rows = bias / zero) ----
    for (int idx = tid; idx < 640; idx += 256) {
        int r = idx >> 2, gc = idx & 3;
        int n = n0 - 31 + r;
        uint4 kh, kl, vh, vl;
        if ((unsigned)n < (unsigned)N_) {
            size_t e = basee + (size_t)n * E_ + gc * 8;
            kh = *(const uint4*)&g_kh[e];
            kl = *(const uint4*)&g_kl[e];
            vh = *(const uint4*)&g_vh[e];
            vl = *(const uint4*)&g_vl[e];
        } else if (n < 0) {
            float4 b0 = *(const float4*)&bias[h * HD_ + gc * 8];
            float4 b1 = *(const float4*)&bias[h * HD_ + gc * 8 + 4];
            uint32_t h0, l0, h1, l1, h2, l2, h3, l3;
            split2(b0.x, b0.y, h0, l0);
            split2(b0.z, b0.w, h1, l1);
            split2(b1.x, b1.y, h2, l2);
            split2(b1.z, b1.w, h3, l3);
            kh = make_uint4(h0, h1, h2, h3);
            kl = make_uint4(l0, l1, l2, l3);
            vh = kh; vl = kl;
        } else {
            kh = kl = vh = vl = make_uint4(0, 0, 0, 0);
        }
        uint32_t off = r * 80 + gc * 16;
        *(uint4*)(smem + AK_HI + off) = kh;
        *(uint4*)(smem + AK_LO + off) = kl;
        *(uint4*)(smem + AV_HI + off) = vh;
        *(uint4*)(smem + AV_LO + off) = vl;
    }
    __syncthreads();

    const int g    = tid >> 5;        // warp = 16-query group
    const int lane = tid & 31;
    const int sub = lane >> 3, r8 = lane & 7;
    const int j = lane >> 2;          // fragment row within 16-row tile
    const int cb2 = (lane & 3) * 2;   // fragment col pair base

    // ================= S = Q . K^T (16 x 48, k=32) =================
    float sf[6][4];
    #pragma unroll
    for (int f = 0; f < 6; f++)
        #pragma unroll
        for (int i = 0; i < 4; i++) sf[f][i] = 0.f;

    #pragma unroll
    for (int ks = 0; ks < 2; ks++) {
        int arow = g * 16 + (sub & 1) * 8 + r8;
        uint32_t aoff = arow * 80 + ks * 32 + (sub >> 1) * 16;
        uint32_t qh[4], ql[4];
        LDSM_X4(qh[0], qh[1], qh[2], qh[3], sb + AQ_HI + aoff);
        LDSM_X4(ql[0], ql[1], ql[2], ql[3], sb + AQ_LO + aoff);
        #pragma unroll
        for (int ng = 0; ng < 3; ng++) {
            int brow = g * 16 + ng * 16 + (sub >> 1) * 8 + r8;
            uint32_t boff = brow * 80 + ks * 32 + (sub & 1) * 16;
            uint32_t kh[4], kl[4];
            LDSM_X4(kh[0], kh[1], kh[2], kh[3], sb + AK_HI + boff);
            LDSM_X4(kl[0], kl[1], kl[2], kl[3], sb + AK_LO + boff);
            int f = ng * 2;
            MMA_BF16(sf[f],     qh, &kh[0]);
            MMA_BF16(sf[f + 1], qh, &kh[2]);
            MMA_BF16(sf[f],     qh, &kl[0]);
            MMA_BF16(sf[f + 1], qh, &kl[2]);
            MMA_BF16(sf[f],     ql, &kh[0]);
            MMA_BF16(sf[f + 1], ql, &kh[2]);
        }
    }

    // ================= mask + softmax in registers =================
    // Valid window for query row j: cols c with (c - j) in [0, 31].
    float mx0 = -1e30f, mx1 = -1e30f;
    #pragma unroll
    for (int f = 0; f < 6; f++) {
        int c = f * 8 + cb2;
        float s0 = sf[f][0] * SCALE_;
        float s1 = sf[f][1] * SCALE_;
        float s2 = sf[f][2] * SCALE_;
        float s3 = sf[f][3] * SCALE_;
        if ((unsigned)(c - j) >= 32u)           s0 = -1e30f;
        if ((unsigned)(c + 1 - j) >= 32u)       s1 = -1e30f;
        if ((unsigned)(c - (j + 8)) >= 32u)     s2 = -1e30f;
        if ((unsigned)(c + 1 - (j + 8)) >= 32u) s3 = -1e30f;
        sf[f][0] = s0; sf[f][1] = s1; sf[f][2] = s2; sf[f][3] = s3;
        mx0 = fmaxf(mx0, fmaxf(s0, s1));
        mx1 = fmaxf(mx1, fmaxf(s2, s3));
    }
    mx0 = fmaxf(mx0, __shfl_xor_sync(0xffffffffu, mx0, 1));
    mx0 = fmaxf(mx0, __shfl_xor_sync(0xffffffffu, mx0, 2));
    mx1 = fmaxf(mx1, __shfl_xor_sync(0xffffffffu, mx1, 1));
    mx1 = fmaxf(mx1, __shfl_xor_sync(0xffffffffu, mx1, 2));

    float sm0 = 0.f, sm1 = 0.f;
    #pragma unroll
    for (int f = 0; f < 6; f++) {
        float e0 = __expf(sf[f][0] - mx0);
        float e1 = __expf(sf[f][1] - mx0);
        float e2 = __expf(sf[f][2] - mx1);
        float e3 = __expf(sf[f][3] - mx1);
        sf[f][0] = e0; sf[f][1] = e1; sf[f][2] = e2; sf[f][3] = e3;
        sm0 += e0 + e1;
        sm1 += e2 + e3;
    }
    sm0 += __shfl_xor_sync(0xffffffffu, sm0, 1);
    sm0 += __shfl_xor_sync(0xffffffffu, sm0, 2);
    sm1 += __shfl_xor_sync(0xffffffffu, sm1, 1);
    sm1 += __shfl_xor_sync(0xffffffffu, sm1, 2);
    const float inv0 = 1.f / sm0;
    const float inv1 = 1.f / sm1;

    // ---- P (bf16 hi/lo) repacked directly into A-fragments ----
    uint32_t pah[3][4], pal[3][4];
    #pragma unroll
    for (int kf = 0; kf < 3; kf++) {
        int f0 = kf * 2, f1 = kf * 2 + 1;
        split2(sf[f0][0] * inv0, sf[f0][1] * inv0, pah[kf][0], pal[kf][0]);
        split2(sf[f0][2] * inv1, sf[f0][3] * inv1, pah[kf][1], pal[kf][1]);
        split2(sf[f1][0] * inv0, sf[f1][1] * inv0, pah[kf][2], pal[kf][2]);
        split2(sf[f1][2] * inv1, sf[f1][3] * inv1, pah[kf][3], pal[kf][3]);
    }

    // ================= O = P . V (16 x 32, k=48) =================
    float of[4][4];
    #pragma unroll
    for (int nf = 0; nf < 4; nf++)
        #pragma unroll
        for (int i = 0; i < 4; i++) of[nf][i] = 0.f;

    #pragma unroll
    for (int kf = 0; kf < 3; kf++) {
        #pragma unroll
        for (int dg = 0; dg < 2; dg++) {
            int vrow = g * 16 + kf * 16 + (sub & 1) * 8 + r8;
            uint32_t voff = vrow * 80 + dg * 32 + (sub >> 1) * 16;
            uint32_t vh[4], vl[4];
            LDSM_X4_T(vh[0], vh[1], vh[2], vh[3], sb + AV_HI + voff);
            LDSM_X4_T(vl[0], vl[1], vl[2], vl[3], sb + AV_LO + voff);
            int nf = dg * 2;
            MMA_BF16(of[nf],     pah[kf], &vh[0]);
            MMA_BF16(of[nf + 1], pah[kf], &vh[2]);
            MMA_BF16(of[nf],     pah[kf], &vl[0]);
            MMA_BF16(of[nf + 1], pah[kf], &vl[2]);
            MMA_BF16(of[nf],     pal[kf], &vh[0]);
            MMA_BF16(of[nf + 1], pal[kf], &vh[2]);
        }
    }

    // ---- store output ----
    #pragma unroll
    for (int nf = 0; nf < 4; nf++) {
        int d = nf * 8 + cb2;
        int n = n0 + g * 16 + j;
        float2 o0 = { of[nf][0], of[nf][1] };
        float2 o1 = { of[nf][2], of[nf][3] };
        *(float2*)&out[basee + (size_t)n * E_ + d]       = o0;
        *(float2*)&out[basee + (size_t)(n + 8) * E_ + d] = o1;
    }
}

// ===========================================================================
extern "C" void kernel_launch(void* const* d_in, const int* in_sizes, int n_in,
                              void* d_out, int out_size)
{
    const float* q = (const float*)d_in[0];
    const float* k = (const float*)d_in[1];
    const float* v = (const float*)d_in[2];
    const float* W = (const float*)d_in[3];
    const float* b = (const float*)d_in[4];
    float* out = (float*)d_out;

    cudaFuncSetAttribute(proj_mma_kernel,
                         cudaFuncAttributeMaxDynamicSharedMemorySize, PROJ_SMEM);
    cudaFuncSetAttribute(attn_kernel,
                         cudaFuncAttributeMaxDynamicSharedMemorySize, ATTN_SMEM);

    const int conv_threads = (3 * M_TOT * E_ + WT) / 4;
    convert_kernel<<<(conv_threads + 255) / 256, 256>>>(q, k, v, W);

    dim3 gProj(2, 64, 3);
    proj_mma_kernel<<<gProj, 256, PROJ_SMEM>>>(b);

    dim3 gAttn(N_ / 128, H_, B_);
    attn_kernel<<<gAttn, 256, ATTN_SMEM>>>(b, out);
}